// round 7
// baseline (speedup 1.0000x reference)
#include <cuda_runtime.h>
#include <cuda_bf16.h>

// BayesianMF: per-user Bayesian linear update
//   prec_u = lambda_K + alpha * sum_{j in obs(u)} V_j V_j^T
//   rhs_u  = alpha * sum_j r_j V_j + lambda_K @ mu_K
//   mu_u   = prec_u^{-1} rhs_u ;  L_u = chol(prec_u^{-1}) ; out = mu + L z
//
// chol(P^{-1}) identity: J = reversal permutation, Q = J P J, H = chol(Q).
// Then L = J H^{-T} J = chol(P^{-1}), so L z = J H^{-T} (J z): one backward
// substitution, no explicit inverse, no second Cholesky.
//
// R7 = R6 resubmitted (container infra failure; kernel never ran):
// (a) solve as 16-lane cooperative (row-per-lane Cholesky, transpose captured
// during broadcasts) -> no register spills;
// (b) accum inner loop branch-free (FSEL operand selection), score on TT
// lanes -> 6 shfl/obs, no BSSY/BSYNC per observation.

#define D          16
#define NTRI       136          // 16*17/2
#define ACC_STRIDE 152          // 136 outer + 16 scoresum
#define MAX_USERS  50016
#define NNZ_MAX    1048576
#define ALPHA_F    2.0f
#define FULLM      0xffffffffu

#define TRI(i, j) (((i) * ((i) + 1)) / 2 + (j))

// Scratch (no cudaMalloc allowed)
__device__ __align__(16) float g_acc[(size_t)MAX_USERS * ACC_STRIDE];  // 30.4 MB
__device__ int  g_counts[MAX_USERS];
__device__ int  g_offsets[MAX_USERS];
__device__ int  g_cursors[MAX_USERS];
__device__ int2 g_sorted[NNZ_MAX];                                     // 8 MB

// ---------------------------------------------------------------------------
// Phase 1a: zero per-user counts
// ---------------------------------------------------------------------------
__global__ void zero_counts_kernel(int num_users) {
    int i = blockIdx.x * blockDim.x + threadIdx.x;
    if (i < num_users) g_counts[i] = 0;
}

// Phase 1b: histogram of user_ids
__global__ void hist_kernel(const int* __restrict__ user_ids, int nnz) {
    int i = blockIdx.x * blockDim.x + threadIdx.x;
    if (i < nnz) atomicAdd(&g_counts[user_ids[i]], 1);
}

// Phase 1c: exclusive scan of counts (single block, 1024 threads)
__global__ void scan_kernel(int num_users) {
    __shared__ int sh[1024];
    const int tid = threadIdx.x;
    const int chunk = (num_users + 1023) >> 10;
    const int base = tid * chunk;

    int s = 0;
    for (int j = 0; j < chunk; j++) {
        int idx = base + j;
        if (idx < num_users) s += g_counts[idx];
    }
    sh[tid] = s;
    __syncthreads();
    for (int off = 1; off < 1024; off <<= 1) {
        int val = (tid >= off) ? sh[tid - off] : 0;
        __syncthreads();
        sh[tid] += val;
        __syncthreads();
    }
    int excl = sh[tid] - s;
    for (int j = 0; j < chunk; j++) {
        int idx = base + j;
        if (idx < num_users) {
            g_offsets[idx] = excl;
            g_cursors[idx] = excl;
            excl += g_counts[idx];
        }
    }
}

// Phase 1d: bucket observations into CSR order (item id + rating packed)
__global__ void bucket_kernel(const int*   __restrict__ user_ids,
                              const int*   __restrict__ item_ids,
                              const float* __restrict__ ratings,
                              int nnz) {
    int i = blockIdx.x * blockDim.x + threadIdx.x;
    if (i >= nnz) return;
    int u = user_ids[i];
    int pos = atomicAdd(&g_cursors[u], 1);
    g_sorted[pos] = make_int2(item_ids[i], __float_as_int(ratings[i]));
}

// ---------------------------------------------------------------------------
// Phase 2: warp-per-user accumulation of outer product + score.
// Clique decomposition of the 136-entry lower triangle:
//   lanes 0..3  ("TT"): two 2x2 triangles (6 entries) + 4 score entries
//   lanes 4..31 ("Q") : one 2x2 block (4 entries)
// Inner loop is BRANCH-FREE: per-lane FSEL operand selection, Q lanes
// accumulate zeros in the unused slots. 6 shfl + 10 FMA + ~8 SEL per obs.
// ---------------------------------------------------------------------------
__global__ void accum_kernel(const float* __restrict__ V, int num_users) {
    const int gw   = (blockIdx.x * blockDim.x + threadIdx.x) >> 5;
    const int lane = threadIdx.x & 31;
    if (gw >= num_users) return;

    const int start = g_offsets[gw];
    const int n     = g_counts[gw];

    const bool isTT = (lane < 4);
    int s0, s1, s2, s3;          // shuffle source v-indices
    int d0, d1, d2, d3, d4, d5;  // destination offsets (TT: 6, Q: 4 used)

    if (isTT) {
        const int t = lane;
        s0 = 4 * t; s1 = 4 * t + 1; s2 = 4 * t + 2; s3 = 4 * t + 3;
        d0 = TRI(4 * t,     4 * t);
        d1 = TRI(4 * t + 1, 4 * t);
        d2 = TRI(4 * t + 1, 4 * t + 1);
        d3 = TRI(4 * t + 2, 4 * t + 2);
        d4 = TRI(4 * t + 3, 4 * t + 2);
        d5 = TRI(4 * t + 3, 4 * t + 3);
    } else {
        const int c = lane - 4;
        int i0, k0;
        if (c < 4) {                      // diag block lower-left 2x2
            i0 = 4 * c + 2; k0 = 4 * c;
        } else {                          // off-diag block quadrant
            const int c2 = c - 4;
            const int m = c2 >> 2, q = c2 & 3;
            // (A,B) for m = 0..5: (0,1),(0,2),(0,3),(1,2),(1,3),(2,3)
            const int A = (m < 3) ? 0 : ((m < 5) ? 1 : 2);
            const int B = (m < 3) ? (m + 1) : ((m < 5) ? (m - 1) : 3);
            i0 = 4 * B + 2 * (q >> 1);
            k0 = 4 * A + 2 * (q & 1);
        }
        const int i1 = i0 + 1, k1 = k0 + 1;
        s0 = i0; s1 = i1; s2 = k0; s3 = k1;
        d0 = TRI(i0, k0); d1 = TRI(i0, k1);
        d2 = TRI(i1, k0); d3 = TRI(i1, k1);
        d4 = 0; d5 = 0;
    }

    float a0 = 0.f, a1 = 0.f, a2 = 0.f, a3 = 0.f, a4 = 0.f, a5 = 0.f;
    float a6 = 0.f, a7 = 0.f, a8 = 0.f, a9 = 0.f;   // scores (TT only)

    for (int t0 = 0; t0 < n; t0 += 32) {
        const int rem = n - t0;
        int2 ob = (lane < rem) ? __ldg(&g_sorted[start + t0 + lane])
                               : make_int2(0, 0);
        const int m = rem < 32 ? rem : 32;
#pragma unroll 4
        for (int t = 0; t < m; t++) {
            const int   it = __shfl_sync(FULLM, ob.x, t);
            const float r  = __shfl_sync(FULLM, __int_as_float(ob.y), t);
            const float vl = __ldg(&V[(it << 4) + (lane & 15)]);
            // Per-lane operand shuffles. TT lane t: w0..w3 = v[4t..4t+3];
            // Q lane: w0=v[i0], w1=v[i1], w2=v[k0], w3=v[k1].
            const float w0 = __shfl_sync(FULLM, vl, s0);
            const float w1 = __shfl_sync(FULLM, vl, s1);
            const float w2 = __shfl_sync(FULLM, vl, s2);
            const float w3 = __shfl_sync(FULLM, vl, s3);
            // Branch-free slot operands:
            //   slot0: TT w0*w0 | Q w0*w2      slot1: TT w1*w0 | Q w0*w3
            //   slot2: TT w1*w1 | Q w1*w2      slot3: TT w2*w2 | Q w1*w3
            //   slot4: TT w3*w2 | Q 0          slot5: TT w3*w3 | Q 0
            const float y0 = isTT ? w0 : w2;
            const float x1 = isTT ? w1 : w0;
            const float y1 = isTT ? w0 : w3;
            const float y2 = isTT ? w1 : w2;
            const float x3 = isTT ? w2 : w1;
            const float y3 = isTT ? w2 : w3;
            const float y4 = isTT ? w2 : 0.f;
            const float y5 = isTT ? w3 : 0.f;
            const float re = isTT ? r  : 0.f;
            a0 += w0 * y0;
            a1 += x1 * y1;
            a2 += w1 * y2;
            a3 += x3 * y3;
            a4 += w3 * y4;
            a5 += w3 * y5;
            a6 += re * w0;
            a7 += re * w1;
            a8 += re * w2;
            a9 += re * w3;
        }
    }

    float* acc = g_acc + (size_t)gw * ACC_STRIDE;
    if (isTT) {
        acc[d0] = a0; acc[d1] = a1; acc[d2] = a2;
        acc[d3] = a3; acc[d4] = a4; acc[d5] = a5;
        const int sb = NTRI + 4 * lane;
        acc[sb + 0] = a6; acc[sb + 1] = a7; acc[sb + 2] = a8; acc[sb + 3] = a9;
    } else {
        acc[d0] = a0; acc[d1] = a1; acc[d2] = a2; acc[d3] = a3;
    }
}

// ---------------------------------------------------------------------------
// Phase 3: cooperative solve — 16 lanes per user, 2 users per warp.
// Lane l owns row l of Q/H (16 regs). Left-looking Cholesky with row-j
// broadcasts; transposed copy col[j] = L[j][l] captured for free during the
// broadcasts. Forward solve + two backward solves, all via width-16 shfl.
// ~50 regs/thread, no spills.
// ---------------------------------------------------------------------------
__global__ void solve_kernel(const float* __restrict__ lambdaK,
                             const float* __restrict__ muK,
                             const float* __restrict__ z,
                             float*       __restrict__ out,
                             int num_users) {
    const int tid = blockIdx.x * blockDim.x + threadIdx.x;
    const int grp = tid >> 4;
    const int l   = tid & 15;
    const bool active = (grp < num_users);
    const int u = active ? grp : (num_users - 1);   // clamp; all lanes stay

    const float* S = g_acc + (size_t)u * ACC_STRIDE;
    const int a = 15 - l;                           // original row index

    // Row l of Q = J*prec*J:  Q[l][j] = lambda[a*16+b] + 2*S[TRI(b,a)],
    // b = 15-j, valid (b>=a) iff j<=l.
    float row[D];
#pragma unroll
    for (int j = 0; j < D; j++) {
        const int b = 15 - j;
        float val = 0.f;
        if (j <= l) {
            val = __ldg(&lambdaK[a * D + b])
                + ALPHA_F * __ldg(&S[b * (b + 1) / 2 + a]);
        }
        row[j] = val;
    }

    // rhs (reversed): w = 2*score[a] + dot(lambda[a,:], muK)
    float w;
    {
        float lmu = 0.f;
#pragma unroll
        for (int k = 0; k < D; k++) {
            lmu += __ldg(&lambdaK[a * D + k]) * __ldg(&muK[k]);
        }
        w = ALPHA_F * __ldg(&S[NTRI + a]) + lmu;
    }

    // Cooperative Cholesky. After step j: row[j] = L[l][j] (l>=j),
    // col[j] (on lane l<=j) = L[j][l], myinv = 1/L[l][l].
    float col[D];
    float myinv = 0.f;
#pragma unroll
    for (int j = 0; j < D; j++) {
        float t = row[j];
#pragma unroll
        for (int k = 0; k < j; k++) {
            const float ljk = __shfl_sync(FULLM, row[k], j, 16);
            t -= row[k] * ljk;
            if (l == k) col[j] = ljk;     // transpose capture
        }
        const float ljj  = sqrtf(t);                       // valid on lane j
        const float ljjb = __shfl_sync(FULLM, ljj, j, 16);
        const float inv  = 1.0f / ljjb;
        if (l == j) { row[j] = ljjb; col[j] = ljjb; myinv = inv; }
        else if (l > j) { row[j] = t * inv; }
    }

    // Forward solve H y = w (column sweep)
    float acc = w, y = 0.f;
#pragma unroll
    for (int i = 0; i < D; i++) {
        const float yi = __shfl_sync(FULLM, acc * myinv, i, 16);
        if (l == i) y = yi;
        if (l > i) acc -= row[i] * yi;
    }
    // Backward solve H^T x = y  -> x = Q^{-1} w (reversed mu)
    float acc2 = y, x = 0.f;
#pragma unroll
    for (int i = D - 1; i >= 0; i--) {
        const float xi = __shfl_sync(FULLM, acc2 * myinv, i, 16);
        if (l == i) x = xi;
        if (l < i) acc2 -= col[i] * xi;
    }

    // Sample term: backward solve H^T s = (Jz);  (Jz)_l = z[u*16 + a]
    float accz = __ldg(&z[(size_t)u * D + a]);
    float xs = 0.f;
#pragma unroll
    for (int i = D - 1; i >= 0; i--) {
        const float si = __shfl_sync(FULLM, accz * myinv, i, 16);
        if (l == i) xs = si;
        if (l < i) accz -= col[i] * si;
    }

    // out[u][a] = mu[a] + (Lz)[a] = x_l + xs_l
    if (active) out[(size_t)u * D + a] = x + xs;
}

// ---------------------------------------------------------------------------
extern "C" void kernel_launch(void* const* d_in, const int* in_sizes, int n_in,
                              void* d_out, int out_size) {
    const float* V       = (const float*)d_in[0];
    const float* ratings = (const float*)d_in[1];
    const float* muK     = (const float*)d_in[2];
    const float* lambdaK = (const float*)d_in[3];
    const float* z       = (const float*)d_in[4];
    const int*   uid     = (const int*)d_in[5];
    const int*   iid     = (const int*)d_in[6];

    const int nnz       = in_sizes[5];        // user_ids length
    const int num_users = in_sizes[4] / D;    // z is [U, 16]

    zero_counts_kernel<<<(num_users + 255) / 256, 256>>>(num_users);
    hist_kernel<<<(nnz + 255) / 256, 256>>>(uid, nnz);
    scan_kernel<<<1, 1024>>>(num_users);
    bucket_kernel<<<(nnz + 255) / 256, 256>>>(uid, iid, ratings, nnz);

    const int accum_blocks = (num_users + 7) / 8;            // 8 warps/block
    accum_kernel<<<accum_blocks, 256>>>(V, num_users);

    // 16 users per 256-thread block
    const int solve_blocks = (num_users + 15) / 16;
    solve_kernel<<<solve_blocks, 256>>>(lambdaK, muK, z,
                                        (float*)d_out, num_users);
}